// round 8
// baseline (speedup 1.0000x reference)
#include <cuda_runtime.h>
#include <cstdint>

// Problem constants
#define NB      2
#define N_SRC   131072
#define N_DST   131072
#define E_CNT   524288
#define FDIM    64
#define F4      (FDIM / 4)     // 16 float4 per feature row
#define EPS_F   1e-8f

#define SCAN_BLK   1024
#define SCAN_NBLK  (N_DST / SCAN_BLK)   // 128

#define D_BLK    64         // destinations per gather block
#define PAIR_CAP 2048       // smem pair-staging capacity (avg need: 256)

// ---------------- scratch (__device__ globals; zero-initialized) -------------
// Invariant: every kernel_launch leaves g_cnt and g_cur zeroed (gather resets
// them), so graph replays see identical starting state.
__device__ int   g_cnt[N_DST];        // edges per dst (hist)
__device__ int   g_cur[N_DST];        // fill cursor per dst
__device__ int   g_excl[N_DST];       // block-local exclusive scan of cnt
__device__ int   g_bsum[SCAN_NBLK];   // per-scan-block totals
__device__ int   g_startd[N_DST + 1]; // global CSR start per dst (fill writes)
__device__ int2  g_pair[E_CNT + 8];   // (src, w-bits) sorted by dst (+pad)

// ---------------------------------------------------------------------------
// K1: histogram of dst (g_cnt starts zeroed)
// ---------------------------------------------------------------------------
__global__ void hist_kernel(const int* __restrict__ dst) {
    int e = blockIdx.x * blockDim.x + threadIdx.x;
    if (e < E_CNT) atomicAdd(&g_cnt[dst[e] & (N_DST - 1)], 1);
}

// ---------------------------------------------------------------------------
// K2: per-block EXCLUSIVE scan of cnt (1024/block, 128 blocks), shuffle-based
// ---------------------------------------------------------------------------
__global__ void scanA_kernel() {
    __shared__ int warp_sums[32];
    int tid  = threadIdx.x;
    int i    = blockIdx.x * SCAN_BLK + tid;
    int lane = tid & 31, wid = tid >> 5;

    int v = g_cnt[i];
    int s = v;
#pragma unroll
    for (int ofs = 1; ofs < 32; ofs <<= 1) {
        int t = __shfl_up_sync(0xffffffffu, s, ofs);
        if (lane >= ofs) s += t;
    }
    if (lane == 31) warp_sums[wid] = s;
    __syncthreads();
    if (wid == 0) {
        int ws = warp_sums[lane];
        int ss = ws;
#pragma unroll
        for (int ofs = 1; ofs < 32; ofs <<= 1) {
            int t = __shfl_up_sync(0xffffffffu, ss, ofs);
            if (lane >= ofs) ss += t;
        }
        warp_sums[lane] = ss - ws;
        if (lane == 31) g_bsum[blockIdx.x] = ss;
    }
    __syncthreads();
    int incl = s + warp_sums[wid];
    g_excl[i] = incl - v;
}

// ---------------------------------------------------------------------------
// K3: fill CSR. Each block re-scans the 128 block sums in smem, scatters
// (src, w) pairs, AND writes the final per-dst CSR start (g_startd) so the
// gather kernel needs no scan at all.
// ---------------------------------------------------------------------------
__global__ void fill_kernel(const int* __restrict__ src,
                            const int* __restrict__ dst,
                            const float* __restrict__ w) {
    __shared__ int sh_boff[SCAN_NBLK];
    int tid = threadIdx.x;
    if (tid < SCAN_NBLK) sh_boff[tid] = g_bsum[tid];
    __syncthreads();
#pragma unroll
    for (int ofs = 1; ofs < SCAN_NBLK; ofs <<= 1) {
        int t = 0;
        if (tid < SCAN_NBLK && tid >= ofs) t = sh_boff[tid - ofs];
        __syncthreads();
        if (tid < SCAN_NBLK) sh_boff[tid] += t;
        __syncthreads();
    }

    int e = blockIdx.x * blockDim.x + tid;
    if (e >= E_CNT) return;

    // Fence-post side channel: first N_DST threads write final CSR starts.
    if (e < N_DST) {
        int blk = e >> 10;
        int boff = (blk > 0) ? sh_boff[blk - 1] : 0;
        g_startd[e] = g_excl[e] + boff;
        if (e == 0) g_startd[N_DST] = E_CNT;
    }

    int d = dst[e] & (N_DST - 1);
    int s = src[e] & (N_SRC - 1);
    int blk = d >> 10;
    int boff = (blk > 0) ? sh_boff[blk - 1] : 0;
    int pos = g_excl[d] + boff + atomicAdd(&g_cur[d], 1);
    if (pos >= 0 && pos < E_CNT) {
        g_pair[pos] = make_int2(s, __float_as_int(w[e]));
    }
}

// ---------------------------------------------------------------------------
// K4: gather with block-level CSR staging.
// Block = 256 threads, owns D_BLK=64 contiguous dsts whose pair segments form
// ONE contiguous range of g_pair.
//   Phase A: one coalesced read of 65 fence posts (precomputed by fill).
//   Phase B: bulk coalesced copy of the pair range into smem (cap 2048;
//            global fallback if exceeded — statistically unreachable).
//   Phase C: warp per dst x 8 rounds; simple unrolled loop: LDS pair
//            broadcast + independent LDG.128 x rows + FFMA; one normalization
//            multiply; one STG.128 per lane.
// Resets g_cnt/g_cur for replay determinism.
// ---------------------------------------------------------------------------
__global__ void gather_kernel(const float4* __restrict__ x4,
                              float4* __restrict__ out4) {
    __shared__ int  sh_start[D_BLK + 1];
    __shared__ int2 sh_pair[PAIR_CAP];

    int tid = threadIdx.x;
    int d0  = blockIdx.x * D_BLK;

    // Phase A: fence posts
    if (tid <= D_BLK) sh_start[tid] = g_startd[d0 + tid];
    // Reset scratch for the next graph replay
    if (tid < D_BLK) { g_cnt[d0 + tid] = 0; g_cur[d0 + tid] = 0; }
    __syncthreads();

    // Phase B: stage the block's contiguous pair range
    int base  = sh_start[0];
    int total = sh_start[D_BLK] - base;
    bool fit  = (total <= PAIR_CAP);
    if (fit) {
        for (int i = tid; i < total; i += 256) sh_pair[i] = g_pair[base + i];
    }
    __syncthreads();

    // Phase C: warp per dst, 8 dsts per warp
    int wid  = tid >> 5;
    int lane = tid & 31;
    int b  = lane >> 4;
    int fi = lane & 15;
    const char* xb = (const char*)(x4 + (size_t)b * N_SRC * F4 + fi);

#pragma unroll 1
    for (int k = 0; k < D_BLK / 8; k++) {
        int dl = wid * (D_BLK / 8) + k;
        int s0 = sh_start[dl];
        int n  = sh_start[dl + 1] - s0;

        const int2* pp = fit ? (const int2*)(sh_pair + (s0 - base))
                             : (const int2*)(g_pair + s0);

        float4 acc = make_float4(0.f, 0.f, 0.f, 0.f);
        float  sumw = 0.f;

#pragma unroll 4
        for (int i = 0; i < n; i++) {
            int2 p = pp[i];
            float w  = __int_as_float(p.y);
            float4 v = *(const float4*)(xb + ((unsigned)p.x << 8));
            acc.x += w * v.x;
            acc.y += w * v.y;
            acc.z += w * v.z;
            acc.w += w * v.w;
            sumw  += w;
        }

        float inv = (n > 0) ? (1.0f / (sumw + EPS_F)) : 0.0f;
        float4 o = make_float4(acc.x * inv, acc.y * inv, acc.z * inv, acc.w * inv);
        out4[(size_t)b * N_DST * F4 + (size_t)(d0 + dl) * F4 + fi] = o;
    }
}

// ---------------------------------------------------------------------------
// Launch. Inputs identified by element count:
//   x: 16,777,216 f32   edge_index: 1,048,576 i32   weights: 524,288 f32
// edge_index is [2, E]: first E = src, next E = dst. Output f32 (B,N_DST,F).
// ---------------------------------------------------------------------------
extern "C" void kernel_launch(void* const* d_in, const int* in_sizes, int n_in,
                              void* d_out, int out_size) {
    const float* x   = nullptr;
    const int*   ei  = nullptr;
    const float* wts = nullptr;

    for (int i = 0; i < n_in; i++) {
        if (in_sizes[i] == NB * N_SRC * FDIM)      x   = (const float*)d_in[i];
        else if (in_sizes[i] == 2 * E_CNT)         ei  = (const int*)d_in[i];
        else if (in_sizes[i] == E_CNT)             wts = (const float*)d_in[i];
    }
    if (!x)   x   = (const float*)d_in[0];
    if (!ei)  ei  = (const int*)d_in[1];
    if (!wts) wts = (const float*)d_in[2];

    const int* src = ei;
    const int* dst = ei + E_CNT;
    float* out = (float*)d_out;

    hist_kernel<<<(E_CNT + 255) / 256, 256>>>(dst);
    scanA_kernel<<<SCAN_NBLK, SCAN_BLK>>>();
    fill_kernel<<<(E_CNT + 255) / 256, 256>>>(src, dst, wts);
    gather_kernel<<<N_DST / D_BLK, 256>>>((const float4*)x, (float4*)out);
}

// round 9
// speedup vs baseline: 1.1523x; 1.1523x over previous
#include <cuda_runtime.h>
#include <cstdint>

// Problem constants
#define NB      2
#define N_SRC   131072
#define N_DST   131072
#define E_CNT   524288
#define FDIM    64
#define F4      (FDIM / 4)     // 16 float4 per feature row
#define EPS_F   1e-8f

#define SCAN_BLK   1024
#define SCAN_NBLK  (N_DST / SCAN_BLK)   // 128

#define D_BLK    64         // destinations per gather block
#define PAIR_CAP 2048       // smem pair-staging capacity (avg need: 256)

// ---------------- scratch (__device__ globals; zero-initialized) -------------
// Invariant: every kernel_launch leaves g_cnt and g_cur zeroed (gather resets
// them), so graph replays see identical starting state.
__device__ int   g_cnt[N_DST];        // edges per dst (hist)
__device__ int   g_cur[N_DST];        // fill cursor per dst
__device__ int   g_excl[N_DST];       // block-local exclusive scan of cnt
__device__ int   g_bsum[SCAN_NBLK];   // per-scan-block totals
__device__ int   g_startd[N_DST + 1]; // global CSR start per dst (fill writes)
__device__ int2  g_pair[E_CNT + 8];   // (src, w-bits) sorted by dst (+pad)

// ---------------------------------------------------------------------------
// K1: histogram of dst (g_cnt starts zeroed)
// ---------------------------------------------------------------------------
__global__ void hist_kernel(const int* __restrict__ dst) {
    int e = blockIdx.x * blockDim.x + threadIdx.x;
    if (e < E_CNT) atomicAdd(&g_cnt[dst[e] & (N_DST - 1)], 1);
}

// ---------------------------------------------------------------------------
// K2: per-block EXCLUSIVE scan of cnt (1024/block, 128 blocks), shuffle-based
// ---------------------------------------------------------------------------
__global__ void scanA_kernel() {
    __shared__ int warp_sums[32];
    int tid  = threadIdx.x;
    int i    = blockIdx.x * SCAN_BLK + tid;
    int lane = tid & 31, wid = tid >> 5;

    int v = g_cnt[i];
    int s = v;
#pragma unroll
    for (int ofs = 1; ofs < 32; ofs <<= 1) {
        int t = __shfl_up_sync(0xffffffffu, s, ofs);
        if (lane >= ofs) s += t;
    }
    if (lane == 31) warp_sums[wid] = s;
    __syncthreads();
    if (wid == 0) {
        int ws = warp_sums[lane];
        int ss = ws;
#pragma unroll
        for (int ofs = 1; ofs < 32; ofs <<= 1) {
            int t = __shfl_up_sync(0xffffffffu, ss, ofs);
            if (lane >= ofs) ss += t;
        }
        warp_sums[lane] = ss - ws;
        if (lane == 31) g_bsum[blockIdx.x] = ss;
    }
    __syncthreads();
    int incl = s + warp_sums[wid];
    g_excl[i] = incl - v;
}

// ---------------------------------------------------------------------------
// K3: fill CSR. Each block re-scans the 128 block sums in smem, scatters
// (src, w) pairs, AND writes the final per-dst CSR start (g_startd) so the
// gather kernel needs no scan at all.
// ---------------------------------------------------------------------------
__global__ void fill_kernel(const int* __restrict__ src,
                            const int* __restrict__ dst,
                            const float* __restrict__ w) {
    __shared__ int sh_boff[SCAN_NBLK];
    int tid = threadIdx.x;
    if (tid < SCAN_NBLK) sh_boff[tid] = g_bsum[tid];
    __syncthreads();
#pragma unroll
    for (int ofs = 1; ofs < SCAN_NBLK; ofs <<= 1) {
        int t = 0;
        if (tid < SCAN_NBLK && tid >= ofs) t = sh_boff[tid - ofs];
        __syncthreads();
        if (tid < SCAN_NBLK) sh_boff[tid] += t;
        __syncthreads();
    }

    int e = blockIdx.x * blockDim.x + tid;
    if (e >= E_CNT) return;

    // Fence-post side channel: first N_DST threads write final CSR starts.
    if (e < N_DST) {
        int blk = e >> 10;
        int boff = (blk > 0) ? sh_boff[blk - 1] : 0;
        g_startd[e] = g_excl[e] + boff;
        if (e == 0) g_startd[N_DST] = E_CNT;
    }

    int d = dst[e] & (N_DST - 1);
    int s = src[e] & (N_SRC - 1);
    int blk = d >> 10;
    int boff = (blk > 0) ? sh_boff[blk - 1] : 0;
    int pos = g_excl[d] + boff + atomicAdd(&g_cur[d], 1);
    if (pos >= 0 && pos < E_CNT) {
        g_pair[pos] = make_int2(s, __float_as_int(w[e]));
    }
}

// ---------------------------------------------------------------------------
// K4: gather with block-level CSR staging.
// Block = 256 threads, owns D_BLK=64 contiguous dsts (one contiguous g_pair
// range).
//   Phase A: one coalesced read of 65 precomputed fence posts.
//   Phase B: bulk coalesced copy of the pair range into smem.
//   Phase C: warp per dst x 8 rounds. Inner loop = explicit 8-wide batches:
//            batch-load 8 pairs FIRST (independent LDS), THEN 8 independent
//            LDG.128 x rows + FFMA. This ordering is what creates MLP; a
//            rolled loop serializes LDS->LDG per edge (R8 regression).
// Resets g_cnt/g_cur for replay determinism.
// ---------------------------------------------------------------------------
__global__ void gather_kernel(const float4* __restrict__ x4,
                              float4* __restrict__ out4) {
    __shared__ int  sh_start[D_BLK + 1];
    __shared__ int2 sh_pair[PAIR_CAP];

    int tid = threadIdx.x;
    int d0  = blockIdx.x * D_BLK;

    // Phase A: fence posts
    if (tid <= D_BLK) sh_start[tid] = g_startd[d0 + tid];
    // Reset scratch for the next graph replay
    if (tid < D_BLK) { g_cnt[d0 + tid] = 0; g_cur[d0 + tid] = 0; }
    __syncthreads();

    // Phase B: stage the block's contiguous pair range
    int base  = sh_start[0];
    int total = sh_start[D_BLK] - base;
    bool fit  = (total <= PAIR_CAP);
    if (fit) {
        for (int i = tid; i < total; i += 256) sh_pair[i] = g_pair[base + i];
    }
    __syncthreads();

    // Phase C: warp per dst, 8 dsts per warp
    int wid  = tid >> 5;
    int lane = tid & 31;
    int b  = lane >> 4;
    int fi = lane & 15;
    const char* xb = (const char*)(x4 + (size_t)b * N_SRC * F4 + fi);

#pragma unroll 1
    for (int k = 0; k < D_BLK / 8; k++) {
        int dl = wid * (D_BLK / 8) + k;
        int s0 = sh_start[dl];
        int n  = sh_start[dl + 1] - s0;

        const int2* pp = fit ? (const int2*)(sh_pair + (s0 - base))
                             : (const int2*)(g_pair + s0);

        float4 acc = make_float4(0.f, 0.f, 0.f, 0.f);
        float  sumw = 0.f;

        for (int bb = 0; bb < n; bb += 8) {
            // batch-load up to 8 pairs (independent LDS, predicated)
            int2 p[8];
#pragma unroll
            for (int j = 0; j < 8; j++) {
                p[j] = (bb + j < n) ? pp[bb + j] : make_int2(0, 0);
            }
            // then 8 independent LDG.128 + FFMA (guarded)
#pragma unroll
            for (int j = 0; j < 8; j++) {
                if (bb + j < n) {
                    float w  = __int_as_float(p[j].y);
                    float4 v = *(const float4*)(xb + ((unsigned)p[j].x << 8));
                    acc.x += w * v.x;
                    acc.y += w * v.y;
                    acc.z += w * v.z;
                    acc.w += w * v.w;
                    sumw  += w;
                }
            }
        }

        float inv = (n > 0) ? (1.0f / (sumw + EPS_F)) : 0.0f;
        float4 o = make_float4(acc.x * inv, acc.y * inv, acc.z * inv, acc.w * inv);
        out4[(size_t)b * N_DST * F4 + (size_t)(d0 + dl) * F4 + fi] = o;
    }
}

// ---------------------------------------------------------------------------
// Launch. Inputs identified by element count:
//   x: 16,777,216 f32   edge_index: 1,048,576 i32   weights: 524,288 f32
// edge_index is [2, E]: first E = src, next E = dst. Output f32 (B,N_DST,F).
// ---------------------------------------------------------------------------
extern "C" void kernel_launch(void* const* d_in, const int* in_sizes, int n_in,
                              void* d_out, int out_size) {
    const float* x   = nullptr;
    const int*   ei  = nullptr;
    const float* wts = nullptr;

    for (int i = 0; i < n_in; i++) {
        if (in_sizes[i] == NB * N_SRC * FDIM)      x   = (const float*)d_in[i];
        else if (in_sizes[i] == 2 * E_CNT)         ei  = (const int*)d_in[i];
        else if (in_sizes[i] == E_CNT)             wts = (const float*)d_in[i];
    }
    if (!x)   x   = (const float*)d_in[0];
    if (!ei)  ei  = (const int*)d_in[1];
    if (!wts) wts = (const float*)d_in[2];

    const int* src = ei;
    const int* dst = ei + E_CNT;
    float* out = (float*)d_out;

    hist_kernel<<<(E_CNT + 255) / 256, 256>>>(dst);
    scanA_kernel<<<SCAN_NBLK, SCAN_BLK>>>();
    fill_kernel<<<(E_CNT + 255) / 256, 256>>>(src, dst, wts);
    gather_kernel<<<N_DST / D_BLK, 256>>>((const float4*)x, (float4*)out);
}

// round 10
// speedup vs baseline: 1.1679x; 1.0136x over previous
#include <cuda_runtime.h>
#include <cstdint>

// Problem constants
#define NB      2
#define N_SRC   131072
#define N_DST   131072
#define E_CNT   524288
#define FDIM    64
#define F4      (FDIM / 4)     // 16 float4 per feature row
#define EPS_F   1e-8f

#define SCAN_BLK   1024
#define SCAN_NBLK  (N_DST / SCAN_BLK)   // 128

#define D_BLK    64         // destinations per gather block
#define PAIR_CAP 2048       // smem pair-staging capacity (avg need: 256)

// ---------------- scratch (__device__ globals; zero-initialized) -------------
// Invariant: every kernel_launch leaves g_cnt and g_cur zeroed (gather resets
// them), so graph replays see identical starting state.
__device__ int   g_cnt[N_DST];        // edges per dst (hist)
__device__ int   g_cur[N_DST];        // fill cursor per dst
__device__ int   g_excl[N_DST];       // block-local exclusive scan of cnt
__device__ int   g_bsum[SCAN_NBLK];   // per-scan-block totals
__device__ int   g_startd[N_DST + 1]; // global CSR start per dst (fill writes)
__device__ int2  g_pair[E_CNT + 8];   // (src byte-offset, w-bits) sorted by dst

// ---------------------------------------------------------------------------
// K1: histogram of dst (g_cnt starts zeroed)
// ---------------------------------------------------------------------------
__global__ void hist_kernel(const int* __restrict__ dst) {
    int e = blockIdx.x * blockDim.x + threadIdx.x;
    if (e < E_CNT) atomicAdd(&g_cnt[dst[e] & (N_DST - 1)], 1);
}

// ---------------------------------------------------------------------------
// K2: per-block EXCLUSIVE scan of cnt (1024/block, 128 blocks), shuffle-based
// ---------------------------------------------------------------------------
__global__ void scanA_kernel() {
    __shared__ int warp_sums[32];
    int tid  = threadIdx.x;
    int i    = blockIdx.x * SCAN_BLK + tid;
    int lane = tid & 31, wid = tid >> 5;

    int v = g_cnt[i];
    int s = v;
#pragma unroll
    for (int ofs = 1; ofs < 32; ofs <<= 1) {
        int t = __shfl_up_sync(0xffffffffu, s, ofs);
        if (lane >= ofs) s += t;
    }
    if (lane == 31) warp_sums[wid] = s;
    __syncthreads();
    if (wid == 0) {
        int ws = warp_sums[lane];
        int ss = ws;
#pragma unroll
        for (int ofs = 1; ofs < 32; ofs <<= 1) {
            int t = __shfl_up_sync(0xffffffffu, ss, ofs);
            if (lane >= ofs) ss += t;
        }
        warp_sums[lane] = ss - ws;
        if (lane == 31) g_bsum[blockIdx.x] = ss;
    }
    __syncthreads();
    int incl = s + warp_sums[wid];
    g_excl[i] = incl - v;
}

// ---------------------------------------------------------------------------
// K3: fill CSR. Each block re-scans the 128 block sums in smem, scatters
// (src-byte-offset, w) pairs, AND writes the final per-dst CSR start.
// pair.x is pre-scaled to a byte offset (src * 256) so gather does one IADD.
// ---------------------------------------------------------------------------
__global__ void fill_kernel(const int* __restrict__ src,
                            const int* __restrict__ dst,
                            const float* __restrict__ w) {
    __shared__ int sh_boff[SCAN_NBLK];
    int tid = threadIdx.x;
    if (tid < SCAN_NBLK) sh_boff[tid] = g_bsum[tid];
    __syncthreads();
#pragma unroll
    for (int ofs = 1; ofs < SCAN_NBLK; ofs <<= 1) {
        int t = 0;
        if (tid < SCAN_NBLK && tid >= ofs) t = sh_boff[tid - ofs];
        __syncthreads();
        if (tid < SCAN_NBLK) sh_boff[tid] += t;
        __syncthreads();
    }

    int e = blockIdx.x * blockDim.x + tid;
    if (e >= E_CNT) return;

    // Fence-post side channel: first N_DST threads write final CSR starts.
    if (e < N_DST) {
        int blk = e >> 10;
        int boff = (blk > 0) ? sh_boff[blk - 1] : 0;
        g_startd[e] = g_excl[e] + boff;
        if (e == 0) g_startd[N_DST] = E_CNT;
    }

    int d = dst[e] & (N_DST - 1);
    int s = src[e] & (N_SRC - 1);
    int blk = d >> 10;
    int boff = (blk > 0) ? sh_boff[blk - 1] : 0;
    int pos = g_excl[d] + boff + atomicAdd(&g_cur[d], 1);
    if (pos >= 0 && pos < E_CNT) {
        g_pair[pos] = make_int2(s << 8, __float_as_int(w[e]));  // byte offset
    }
}

// ---------------------------------------------------------------------------
// K4: gather with block-level CSR staging + DUAL-SEGMENT MLP.
// Block = 256 threads, owns D_BLK=64 contiguous dsts (one contiguous g_pair
// range).
//   Phase A: one coalesced read of 65 precomputed fence posts.
//   Phase B: bulk coalesced copy of the pair range into smem.
//   Phase C: warp processes its 8 dsts as 4 rounds x 2 CONCURRENT dsts:
//            independent accumulators, interleaved pair-LDS batches, then
//            both dsts' independent LDG.128 sets -> ~2x loads in flight.
// Resets g_cnt/g_cur for replay determinism.
// ---------------------------------------------------------------------------
__global__ void gather_kernel(const float4* __restrict__ x4,
                              float4* __restrict__ out4) {
    __shared__ int  sh_start[D_BLK + 1];
    __shared__ int2 sh_pair[PAIR_CAP];

    int tid = threadIdx.x;
    int d0  = blockIdx.x * D_BLK;

    // Phase A: fence posts
    if (tid <= D_BLK) sh_start[tid] = g_startd[d0 + tid];
    // Reset scratch for the next graph replay
    if (tid < D_BLK) { g_cnt[d0 + tid] = 0; g_cur[d0 + tid] = 0; }
    __syncthreads();

    // Phase B: stage the block's contiguous pair range
    int base  = sh_start[0];
    int total = sh_start[D_BLK] - base;
    bool fit  = (total <= PAIR_CAP);
    if (fit) {
        for (int i = tid; i < total; i += 256) sh_pair[i] = g_pair[base + i];
    }
    __syncthreads();

    // Phase C: warp per 2 concurrent dsts, 4 rounds
    int wid  = tid >> 5;
    int lane = tid & 31;
    int b  = lane >> 4;
    int fi = lane & 15;
    const char* xb = (const char*)(x4 + (size_t)b * N_SRC * F4 + fi);

#pragma unroll 1
    for (int k = 0; k < 4; k++) {
        int dl  = wid * 8 + k * 2;
        int sA  = sh_start[dl];
        int sB  = sh_start[dl + 1];
        int sC  = sh_start[dl + 2];
        int nA  = sB - sA;
        int nB  = sC - sB;

        const int2* ppA = fit ? (const int2*)(sh_pair + (sA - base))
                              : (const int2*)(g_pair + sA);
        const int2* ppB = fit ? (const int2*)(sh_pair + (sB - base))
                              : (const int2*)(g_pair + sB);

        float4 accA = make_float4(0.f, 0.f, 0.f, 0.f);
        float4 accB = make_float4(0.f, 0.f, 0.f, 0.f);
        float  sumA = 0.f, sumB = 0.f;

        int nmax = nA > nB ? nA : nB;
        for (int bb = 0; bb < nmax; bb += 8) {
            // Stage pairs for BOTH dsts first (independent predicated LDS)
            int2 pA[8], pB[8];
#pragma unroll
            for (int j = 0; j < 8; j++) {
                pA[j] = (bb + j < nA) ? ppA[bb + j] : make_int2(0, 0);
                pB[j] = (bb + j < nB) ? ppB[bb + j] : make_int2(0, 0);
            }
            // Then both dsts' LDG.128 + FFMA sets (independent, guarded)
#pragma unroll
            for (int j = 0; j < 8; j++) {
                if (bb + j < nA) {
                    float w  = __int_as_float(pA[j].y);
                    float4 v = *(const float4*)(xb + (unsigned)pA[j].x);
                    accA.x += w * v.x; accA.y += w * v.y;
                    accA.z += w * v.z; accA.w += w * v.w;
                    sumA   += w;
                }
                if (bb + j < nB) {
                    float w  = __int_as_float(pB[j].y);
                    float4 v = *(const float4*)(xb + (unsigned)pB[j].x);
                    accB.x += w * v.x; accB.y += w * v.y;
                    accB.z += w * v.z; accB.w += w * v.w;
                    sumB   += w;
                }
            }
        }

        float invA = (nA > 0) ? (1.0f / (sumA + EPS_F)) : 0.0f;
        float invB = (nB > 0) ? (1.0f / (sumB + EPS_F)) : 0.0f;
        size_t obase = (size_t)b * N_DST * F4 + (size_t)(d0 + dl) * F4 + fi;
        out4[obase]      = make_float4(accA.x * invA, accA.y * invA,
                                       accA.z * invA, accA.w * invA);
        out4[obase + F4] = make_float4(accB.x * invB, accB.y * invB,
                                       accB.z * invB, accB.w * invB);
    }
}

// ---------------------------------------------------------------------------
// Launch. Inputs identified by element count:
//   x: 16,777,216 f32   edge_index: 1,048,576 i32   weights: 524,288 f32
// edge_index is [2, E]: first E = src, next E = dst. Output f32 (B,N_DST,F).
// ---------------------------------------------------------------------------
extern "C" void kernel_launch(void* const* d_in, const int* in_sizes, int n_in,
                              void* d_out, int out_size) {
    const float* x   = nullptr;
    const int*   ei  = nullptr;
    const float* wts = nullptr;

    for (int i = 0; i < n_in; i++) {
        if (in_sizes[i] == NB * N_SRC * FDIM)      x   = (const float*)d_in[i];
        else if (in_sizes[i] == 2 * E_CNT)         ei  = (const int*)d_in[i];
        else if (in_sizes[i] == E_CNT)             wts = (const float*)d_in[i];
    }
    if (!x)   x   = (const float*)d_in[0];
    if (!ei)  ei  = (const int*)d_in[1];
    if (!wts) wts = (const float*)d_in[2];

    const int* src = ei;
    const int* dst = ei + E_CNT;
    float* out = (float*)d_out;

    hist_kernel<<<(E_CNT + 255) / 256, 256>>>(dst);
    scanA_kernel<<<SCAN_NBLK, SCAN_BLK>>>();
    fill_kernel<<<(E_CNT + 255) / 256, 256>>>(src, dst, wts);
    gather_kernel<<<N_DST / D_BLK, 256>>>((const float4*)x, (float4*)out);
}